// round 8
// baseline (speedup 1.0000x reference)
#include <cuda_runtime.h>
#include <cuda_bf16.h>
#include <cstdint>
#include <cstddef>

#define L_SEQ 2048
#define NB 8
#define NROWS 16384   /* NB*L_SEQ */
#define DM 1024
#define HD 120
#define HDP 128

// ---------------- scratch (static device globals; no allocation) ----------------
__device__ float          g_DW[HDP * HDP];
__device__ float          g_CTX[NROWS * HDP];
__device__ __nv_bfloat16  g_CH[NROWS * HDP];
__device__ __nv_bfloat16  g_CL[NROWS * HDP];
__device__ __nv_bfloat16  g_TH[NROWS * HDP];
__device__ __nv_bfloat16  g_TL[NROWS * HDP];
__device__ float          g_KN[NROWS];

// ---------------- helpers ----------------
static __device__ __forceinline__ void mma16816(float c[4],
    uint32_t a0, uint32_t a1, uint32_t a2, uint32_t a3,
    uint32_t b0, uint32_t b1)
{
    asm volatile(
        "mma.sync.aligned.m16n8k16.row.col.f32.bf16.bf16.f32 "
        "{%0,%1,%2,%3}, {%4,%5,%6,%7}, {%8,%9}, {%0,%1,%2,%3};\n"
        : "+f"(c[0]), "+f"(c[1]), "+f"(c[2]), "+f"(c[3])
        : "r"(a0), "r"(a1), "r"(a2), "r"(a3), "r"(b0), "r"(b1));
}

static __device__ __forceinline__ void ldsm_x4(uint32_t& r0, uint32_t& r1,
                                               uint32_t& r2, uint32_t& r3, uint32_t addr)
{
    asm volatile("ldmatrix.sync.aligned.m8n8.x4.shared.b16 {%0,%1,%2,%3}, [%4];"
        : "=r"(r0), "=r"(r1), "=r"(r2), "=r"(r3) : "r"(addr));
}

static __device__ __forceinline__ uint32_t smem_to_u32(const void* p) {
    uint32_t a;
    asm("{ .reg .u64 t; cvta.to.shared.u64 t, %1; cvt.u32.u64 %0, t; }" : "=r"(a) : "l"(p));
    return a;
}

static __device__ __forceinline__ uint32_t pack_bf16(__nv_bfloat16 lo, __nv_bfloat16 hi)
{
    __nv_bfloat162 v;
    v.x = lo; v.y = hi;
    return *reinterpret_cast<uint32_t*>(&v);
}

static __device__ __forceinline__ void split_pair(float x, float y, uint32_t& h, uint32_t& l)
{
    __nv_bfloat16 hx = __float2bfloat16(x);
    __nv_bfloat16 hy = __float2bfloat16(y);
    float rx = x - __bfloat162float(hx);
    float ry = y - __bfloat162float(hy);
    h = pack_bf16(hx, hy);
    l = pack_bf16(__float2bfloat16(rx), __float2bfloat16(ry));
}

// ---------------- kernel 0: DW = W @ W^T ----------------
__global__ void k0_dw(const float* __restrict__ W)
{
    int r = blockIdx.x, j = threadIdx.x;
    float s = 0.f;
    if (r < HD && j < HD) {
        const float* wr = W + r * HD;
        const float* wj = W + j * HD;
        #pragma unroll 8
        for (int k = 0; k < HD; k++) s = fmaf(__ldg(wr + k), __ldg(wj + k), s);
    }
    g_DW[r * HDP + j] = s;
}

// ---------------- kernel 1a: ctx = q @ Wq^T + bias (split-bf16, ldmatrix) ----------------
#define TROW1 144   /* 72 bf16 per row; stride 36 words -> conflict-free ldsm */
#define K1A_SMEM (4 * 128 * TROW1)
__global__ __launch_bounds__(256) void k1_ctx(const float* __restrict__ q,
                                              const float* __restrict__ wq,
                                              const float* __restrict__ bias)
{
    extern __shared__ char sm1[];
    char* sQh = sm1;
    char* sQl = sm1 + 128 * TROW1;
    char* sWh = sm1 + 2 * 128 * TROW1;
    char* sWl = sm1 + 3 * 128 * TROW1;
    const uint32_t uQh = smem_to_u32(sQh);
    const uint32_t uQl = smem_to_u32(sQl);
    const uint32_t uWh = smem_to_u32(sWh);
    const uint32_t uWl = smem_to_u32(sWl);

    const int tid  = threadIdx.x;
    const int w    = tid >> 5;
    const int lane = tid & 31;
    const int grp  = lane >> 2;
    const int qd   = lane & 3;
    const int rb   = blockIdx.x * 128;

    const int sel = lane >> 3, r8 = lane & 7;
    const uint32_t aOff = (uint32_t)(w * 16 + ((sel & 1) << 3) + r8) * TROW1 + ((sel >> 1) << 4);
    const uint32_t bOff = (uint32_t)(((sel >> 1) << 3) + r8) * TROW1 + ((sel & 1) << 4);

    float acc[16][4];
    #pragma unroll
    for (int i = 0; i < 16; i++) { acc[i][0] = acc[i][1] = acc[i][2] = acc[i][3] = 0.f; }

    for (int kt = 0; kt < 16; kt++) {
        const int kb = kt * 64;
        __syncthreads();
        #pragma unroll
        for (int u = 0; u < 8; u++) {
            int idx = tid + u * 256;
            int row = idx >> 4, c4 = (idx & 15) * 4;
            float4 v = *reinterpret_cast<const float4*>(q + (size_t)(rb + row) * DM + kb + c4);
            uint32_t h01, l01, h23, l23;
            split_pair(v.x, v.y, h01, l01);
            split_pair(v.z, v.w, h23, l23);
            *reinterpret_cast<uint32_t*>(sQh + row * TROW1 + c4 * 2)     = h01;
            *reinterpret_cast<uint32_t*>(sQh + row * TROW1 + c4 * 2 + 4) = h23;
            *reinterpret_cast<uint32_t*>(sQl + row * TROW1 + c4 * 2)     = l01;
            *reinterpret_cast<uint32_t*>(sQl + row * TROW1 + c4 * 2 + 4) = l23;

            float4 wv = make_float4(0.f, 0.f, 0.f, 0.f);
            if (row < HD)
                wv = *reinterpret_cast<const float4*>(wq + (size_t)row * DM + kb + c4);
            split_pair(wv.x, wv.y, h01, l01);
            split_pair(wv.z, wv.w, h23, l23);
            *reinterpret_cast<uint32_t*>(sWh + row * TROW1 + c4 * 2)     = h01;
            *reinterpret_cast<uint32_t*>(sWh + row * TROW1 + c4 * 2 + 4) = h23;
            *reinterpret_cast<uint32_t*>(sWl + row * TROW1 + c4 * 2)     = l01;
            *reinterpret_cast<uint32_t*>(sWl + row * TROW1 + c4 * 2 + 4) = l23;
        }
        __syncthreads();

        #pragma unroll
        for (int ks = 0; ks < 4; ks++) {
            uint32_t ah0, ah1, ah2, ah3, al0, al1, al2, al3;
            ldsm_x4(ah0, ah1, ah2, ah3, uQh + aOff + ks * 32);
            ldsm_x4(al0, al1, al2, al3, uQl + aOff + ks * 32);
            #pragma unroll
            for (int ntp = 0; ntp < 8; ntp++) {
                uint32_t bh0, bh1, bh2, bh3, bl0, bl1, bl2, bl3;
                const uint32_t bb = (uint32_t)(ntp * 16) * TROW1 + bOff + ks * 32;
                ldsm_x4(bh0, bh1, bh2, bh3, uWh + bb);
                ldsm_x4(bl0, bl1, bl2, bl3, uWl + bb);
                mma16816(acc[2 * ntp],     ah0, ah1, ah2, ah3, bh0, bh1);
                mma16816(acc[2 * ntp],     ah0, ah1, ah2, ah3, bl0, bl1);
                mma16816(acc[2 * ntp],     al0, al1, al2, al3, bh0, bh1);
                mma16816(acc[2 * ntp + 1], ah0, ah1, ah2, ah3, bh2, bh3);
                mma16816(acc[2 * ntp + 1], ah0, ah1, ah2, ah3, bl2, bl3);
                mma16816(acc[2 * ntp + 1], al0, al1, al2, al3, bh2, bh3);
            }
        }
    }

    const int R0 = rb + w * 16 + grp, R1 = R0 + 8;
    #pragma unroll
    for (int nt = 0; nt < 16; nt++) {
        int c = nt * 8 + 2 * qd;
        float b0 = (c     < HD) ? __ldg(bias + c)     : 0.f;
        float b1 = (c + 1 < HD) ? __ldg(bias + c + 1) : 0.f;
        float v00 = acc[nt][0] + b0, v01 = acc[nt][1] + b1;
        float v10 = acc[nt][2] + b0, v11 = acc[nt][3] + b1;
        *reinterpret_cast<float2*>(g_CTX + (size_t)R0 * HDP + c) = make_float2(v00, v01);
        *reinterpret_cast<float2*>(g_CTX + (size_t)R1 * HDP + c) = make_float2(v10, v11);
        uint32_t h, l;
        split_pair(v00, v01, h, l);
        *reinterpret_cast<uint32_t*>(g_CH + (size_t)R0 * HDP + c) = h;
        *reinterpret_cast<uint32_t*>(g_CL + (size_t)R0 * HDP + c) = l;
        split_pair(v10, v11, h, l);
        *reinterpret_cast<uint32_t*>(g_CH + (size_t)R1 * HDP + c) = h;
        *reinterpret_cast<uint32_t*>(g_CL + (size_t)R1 * HDP + c) = l;
    }
}

// ---------------- kernel 1b: trans = ctx @ DW, norms, kn, trans splits ----------------
__global__ __launch_bounds__(128) void k1_trans(const float* __restrict__ prec)
{
    __shared__ float cs[128 * 16];
    __shared__ float red[64];
    const int n  = threadIdx.x;
    const int rb = blockIdx.x * 16;

    #pragma unroll
    for (int u = 0; u < 16; u++) {
        int idx = n + u * 128;
        int r = idx >> 7, k = idx & 127;
        cs[k * 16 + r] = g_CTX[(size_t)(rb + r) * HDP + k];
    }
    __syncthreads();

    float acc[16];
    #pragma unroll
    for (int r = 0; r < 16; r++) acc[r] = 0.f;

    for (int k = 0; k < HDP; k++) {
        float dw = g_DW[k * HDP + n];
        const float4* c4 = reinterpret_cast<const float4*>(cs + k * 16);
        float4 a = c4[0], b = c4[1], c = c4[2], d = c4[3];
        acc[0]  = fmaf(a.x, dw, acc[0]);  acc[1]  = fmaf(a.y, dw, acc[1]);
        acc[2]  = fmaf(a.z, dw, acc[2]);  acc[3]  = fmaf(a.w, dw, acc[3]);
        acc[4]  = fmaf(b.x, dw, acc[4]);  acc[5]  = fmaf(b.y, dw, acc[5]);
        acc[6]  = fmaf(b.z, dw, acc[6]);  acc[7]  = fmaf(b.w, dw, acc[7]);
        acc[8]  = fmaf(c.x, dw, acc[8]);  acc[9]  = fmaf(c.y, dw, acc[9]);
        acc[10] = fmaf(c.z, dw, acc[10]); acc[11] = fmaf(c.w, dw, acc[11]);
        acc[12] = fmaf(d.x, dw, acc[12]); acc[13] = fmaf(d.y, dw, acc[13]);
        acc[14] = fmaf(d.z, dw, acc[14]); acc[15] = fmaf(d.w, dw, acc[15]);
    }

    const int lane = n & 31, wrp = n >> 5;
    #pragma unroll
    for (int r = 0; r < 16; r++) {
        float pr = acc[r] * cs[n * 16 + r];
        #pragma unroll
        for (int o = 16; o > 0; o >>= 1) pr += __shfl_xor_sync(0xffffffffu, pr, o);
        if (lane == 0) red[r * 4 + wrp] = pr;
    }
    __syncthreads();
    if (n < 16) {
        float p  = __ldg(prec);
        float nm = red[n * 4] + red[n * 4 + 1] + red[n * 4 + 2] + red[n * 4 + 3];
        g_KN[rb + n] = -0.5f * p * p * nm;
    }

    #pragma unroll
    for (int r = 0; r < 16; r++) {
        float v = acc[r];
        __nv_bfloat16 h = __float2bfloat16(v);
        __nv_bfloat16 l = __float2bfloat16(v - __bfloat162float(h));
        g_TH[(size_t)(rb + r) * HDP + n] = h;
        g_TL[(size_t)(rb + r) * HDP + n] = l;
    }
}

// ---------------- kernel 2: single-pass Gram + RBF + fused normalize ----------------
// 64 A-rows per CTA (grid 256), 2 CTAs/SM for cross-CTA pipe overlap.
// SMEM: A hi/lo 64x272B + B hi/lo 128x272B = 103 KB.
#define TROW 272
#define A_TILE_B (64 * TROW)     /* 17408 */
#define B_TILE_B (128 * TROW)    /* 34816 */
#define K2_SMEM_BYTES (2 * A_TILE_B + 2 * B_TILE_B + 1024)

static __device__ __forceinline__ void load_tile_rows(const __nv_bfloat16* __restrict__ src,
                                                      int rowbase, char* dst, int tid, int nrows)
{
    const int total = nrows * 16;
    for (int idx = tid; idx < total; idx += 256) {
        int row = idx >> 4, c8 = idx & 15;
        uint4 v = *reinterpret_cast<const uint4*>(src + (size_t)(rowbase + row) * HDP + c8 * 8);
        *reinterpret_cast<uint4*>(dst + row * TROW + c8 * 16) = v;
    }
}

__global__ __launch_bounds__(256, 2) void k2_attn(const float* __restrict__ prec,
                                                  float* __restrict__ out)
{
    extern __shared__ char sm2[];
    char* sAh = sm2;
    char* sAl = sm2 + A_TILE_B;
    char* sBh = sm2 + 2 * A_TILE_B;
    char* sBl = sm2 + 2 * A_TILE_B + B_TILE_B;
    float* sKnj = reinterpret_cast<float*>(sm2 + 2 * A_TILE_B + 2 * B_TILE_B);
    float* sSum = reinterpret_cast<float*>(sm2 + 2 * A_TILE_B + 2 * B_TILE_B + 512); // [128]

    const uint32_t uAh = smem_to_u32(sAh);
    const uint32_t uAl = smem_to_u32(sAl);
    const uint32_t uBh = smem_to_u32(sBh);
    const uint32_t uBl = smem_to_u32(sBl);

    const int tid  = threadIdx.x;
    const int wid  = tid >> 5;
    const int lane = tid & 31;
    const int grp  = lane >> 2;
    const int qd   = lane & 3;
    const int wr   = wid & 3;        // row group: rows wr*16 .. wr*16+15
    const int wc   = wid >> 2;       // col half: cols wc*64 .. wc*64+63
    const int bt   = blockIdx.x;
    const int b    = bt >> 5;        // 32 row-tiles of 64 per batch
    const int rt   = bt & 31;
    const int rowg = b * L_SEQ + rt * 64;

    const int sel = lane >> 3, r8 = lane & 7;
    const uint32_t aOff = (uint32_t)(wr * 16 + ((sel & 1) << 3) + r8) * TROW + ((sel >> 1) << 4);
    const uint32_t bOff = (uint32_t)(((sel >> 1) << 3) + r8) * TROW + ((sel & 1) << 4);

    // ---- A tiles (resident, 64 rows) ----
    load_tile_rows(g_TH, rowg, sAh, tid, 64);
    load_tile_rows(g_TL, rowg, sAl, tid, 64);

    const float p     = __ldg(prec);
    const float scale = p * p;
    const int   ra    = wr * 16 + grp;          // local row 0..63
    const int   iloc0 = rt * 64 + ra;           // row within batch
    const int   iloc1 = iloc0 + 8;
    const float kni0  = g_KN[rowg + ra];
    const float kni1  = g_KN[rowg + ra + 8];
    const size_t outbase = (size_t)b * L_SEQ * L_SEQ;
    const float E = 2.718281828459045f;

    float sum0 = 0.f, sum1 = 0.f;

    for (int jt = 0; jt < 16; jt++) {
        __syncthreads();
        const int jb = b * L_SEQ + jt * 128;
        load_tile_rows(g_CH, jb, sBh, tid, 128);
        load_tile_rows(g_CL, jb, sBl, tid, 128);
        if (tid < 128) sKnj[tid] = g_KN[jb + tid];
        __syncthreads();

        float acc[8][4];
        #pragma unroll
        for (int i = 0; i < 8; i++) { acc[i][0] = acc[i][1] = acc[i][2] = acc[i][3] = 0.f; }

        #pragma unroll
        for (int ks = 0; ks < 8; ks++) {
            uint32_t ah0, ah1, ah2, ah3, al0, al1, al2, al3;
            ldsm_x4(ah0, ah1, ah2, ah3, uAh + aOff + ks * 32);
            ldsm_x4(al0, al1, al2, al3, uAl + aOff + ks * 32);
            #pragma unroll
            for (int ntp = 0; ntp < 4; ntp++) {
                uint32_t bh0, bh1, bh2, bh3, bl0, bl1, bl2, bl3;
                const uint32_t bb = (uint32_t)(wc * 64 + ntp * 16) * TROW + bOff + ks * 32;
                ldsm_x4(bh0, bh1, bh2, bh3, uBh + bb);
                ldsm_x4(bl0, bl1, bl2, bl3, uBl + bb);
                mma16816(acc[2 * ntp],     ah0, ah1, ah2, ah3, bh0, bh1);
                mma16816(acc[2 * ntp],     ah0, ah1, ah2, ah3, bl0, bl1);
                mma16816(acc[2 * ntp],     al0, al1, al2, al3, bh0, bh1);
                mma16816(acc[2 * ntp + 1], ah0, ah1, ah2, ah3, bh2, bh3);
                mma16816(acc[2 * ntp + 1], ah0, ah1, ah2, ah3, bl2, bl3);
                mma16816(acc[2 * ntp + 1], al0, al1, al2, al3, bh2, bh3);
            }
        }

        // epilogue: y = exp(exp(kn_i + kn_j + scale*g)); store unnormalized; accumulate sums
        #pragma unroll
        for (int nt = 0; nt < 8; nt++) {
            const int c    = wc * 64 + nt * 8 + 2 * qd;
            const int jloc = jt * 128 + c;
            const float knj0 = sKnj[c], knj1 = sKnj[c + 1];
            float t00 = fmaf(scale, acc[nt][0], kni0 + knj0);
            float t01 = fmaf(scale, acc[nt][1], kni0 + knj1);
            float t10 = fmaf(scale, acc[nt][2], kni1 + knj0);
            float t11 = fmaf(scale, acc[nt][3], kni1 + knj1);
            float y00 = __expf(__expf(t00));
            float y01 = __expf(__expf(t01));
            float y10 = __expf(__expf(t10));
            float y11 = __expf(__expf(t11));
            if (iloc0 == jloc)     y00 = E;
            if (iloc0 == jloc + 1) y01 = E;
            if (iloc1 == jloc)     y10 = E;
            if (iloc1 == jloc + 1) y11 = E;
            sum0 += y00 + y01;
            sum1 += y10 + y11;
            *reinterpret_cast<float2*>(out + outbase + (size_t)iloc0 * L_SEQ + jloc) =
                make_float2(y00, y01);
            *reinterpret_cast<float2*>(out + outbase + (size_t)iloc1 * L_SEQ + jloc) =
                make_float2(y10, y11);
        }
    }

    // ---- row sums: quad-reduce, combine col halves via smem ----
    sum0 += __shfl_xor_sync(0xffffffffu, sum0, 1);
    sum0 += __shfl_xor_sync(0xffffffffu, sum0, 2);
    sum1 += __shfl_xor_sync(0xffffffffu, sum1, 1);
    sum1 += __shfl_xor_sync(0xffffffffu, sum1, 2);
    __syncthreads();
    if (qd == 0) {
        sSum[wc * 64 + ra]     = sum0;
        sSum[wc * 64 + ra + 8] = sum1;
    }
    __syncthreads();
    if (tid < 64) sSum[tid] = 1.0f / (sSum[tid] + sSum[64 + tid]);
    __syncthreads();

    // ---- normalize readback: this CTA's 64x2048 strip ----
    float4* strip = reinterpret_cast<float4*>(out + outbase + (size_t)(rt * 64) * L_SEQ);
    #pragma unroll 4
    for (int it = tid; it < 64 * 512; it += 256) {
        const int row = it >> 9;
        const float s = sSum[row];
        float4 v = strip[it];
        v.x *= s; v.y *= s; v.z *= s; v.w *= s;
        strip[it] = v;
    }
}

// ---------------- launch ----------------
extern "C" void kernel_launch(void* const* d_in, const int* in_sizes, int n_in,
                              void* d_out, int out_size)
{
    (void)in_sizes; (void)n_in; (void)out_size;
    const float* q    = (const float*)d_in[0];
    // d_in[1] = key (unused by the reference computation)
    const float* wq   = (const float*)d_in[2];
    const float* bias = (const float*)d_in[3];
    const float* W    = (const float*)d_in[4];
    const float* prec = (const float*)d_in[5];
    float* out = (float*)d_out;

    cudaFuncSetAttribute(k1_ctx,  cudaFuncAttributeMaxDynamicSharedMemorySize, K1A_SMEM);
    cudaFuncSetAttribute(k2_attn, cudaFuncAttributeMaxDynamicSharedMemorySize, K2_SMEM_BYTES);

    k0_dw<<<HDP, HDP>>>(W);
    k1_ctx<<<NROWS / 128, 256, K1A_SMEM>>>(q, wq, bias);
    k1_trans<<<NROWS / 16, 128>>>(prec);
    k2_attn<<<NROWS / 64, 256, K2_SMEM_BYTES>>>(prec, out);
}

// round 9
// speedup vs baseline: 1.2248x; 1.2248x over previous
#include <cuda_runtime.h>
#include <cuda_bf16.h>
#include <cstdint>
#include <cstddef>

#define L_SEQ 2048
#define NB 8
#define NROWS 16384   /* NB*L_SEQ */
#define DM 1024
#define HD 120
#define HDP 128

// ---------------- scratch (static device globals; no allocation) ----------------
__device__ float          g_DW[HDP * HDP];
__device__ float          g_CTX[NROWS * HDP];
__device__ __nv_bfloat16  g_CH[NROWS * HDP];
__device__ __nv_bfloat16  g_CL[NROWS * HDP];
__device__ __nv_bfloat16  g_TH[NROWS * HDP];
__device__ __nv_bfloat16  g_TL[NROWS * HDP];
__device__ float          g_KN[NROWS];

// ---------------- helpers ----------------
static __device__ __forceinline__ void mma16816(float c[4],
    uint32_t a0, uint32_t a1, uint32_t a2, uint32_t a3,
    uint32_t b0, uint32_t b1)
{
    asm volatile(
        "mma.sync.aligned.m16n8k16.row.col.f32.bf16.bf16.f32 "
        "{%0,%1,%2,%3}, {%4,%5,%6,%7}, {%8,%9}, {%0,%1,%2,%3};\n"
        : "+f"(c[0]), "+f"(c[1]), "+f"(c[2]), "+f"(c[3])
        : "r"(a0), "r"(a1), "r"(a2), "r"(a3), "r"(b0), "r"(b1));
}

static __device__ __forceinline__ void ldsm_x4(uint32_t& r0, uint32_t& r1,
                                               uint32_t& r2, uint32_t& r3, uint32_t addr)
{
    asm volatile("ldmatrix.sync.aligned.m8n8.x4.shared.b16 {%0,%1,%2,%3}, [%4];"
        : "=r"(r0), "=r"(r1), "=r"(r2), "=r"(r3) : "r"(addr));
}

static __device__ __forceinline__ uint32_t smem_to_u32(const void* p) {
    uint32_t a;
    asm("{ .reg .u64 t; cvta.to.shared.u64 t, %1; cvt.u32.u64 %0, t; }" : "=r"(a) : "l"(p));
    return a;
}

static __device__ __forceinline__ void cp_async16(uint32_t dst, const void* src)
{
    asm volatile("cp.async.cg.shared.global [%0], [%1], 16;"
        :: "r"(dst), "l"(__cvta_generic_to_global(src)));
}
#define CP_COMMIT() asm volatile("cp.async.commit_group;" ::: "memory")
#define CP_WAIT(n)  asm volatile("cp.async.wait_group %0;" :: "n"(n) : "memory")

static __device__ __forceinline__ uint32_t pack_bf16(__nv_bfloat16 lo, __nv_bfloat16 hi)
{
    __nv_bfloat162 v;
    v.x = lo; v.y = hi;
    return *reinterpret_cast<uint32_t*>(&v);
}

static __device__ __forceinline__ void split_pair(float x, float y, uint32_t& h, uint32_t& l)
{
    __nv_bfloat16 hx = __float2bfloat16(x);
    __nv_bfloat16 hy = __float2bfloat16(y);
    float rx = x - __bfloat162float(hx);
    float ry = y - __bfloat162float(hy);
    h = pack_bf16(hx, hy);
    l = pack_bf16(__float2bfloat16(rx), __float2bfloat16(ry));
}

// ---------------- kernel 0: DW = W @ W^T ----------------
__global__ void k0_dw(const float* __restrict__ W)
{
    int r = blockIdx.x, j = threadIdx.x;
    float s = 0.f;
    if (r < HD && j < HD) {
        const float* wr = W + r * HD;
        const float* wj = W + j * HD;
        #pragma unroll 8
        for (int k = 0; k < HD; k++) s = fmaf(__ldg(wr + k), __ldg(wj + k), s);
    }
    g_DW[r * HDP + j] = s;
}

// ---------------- kernel 1a: ctx = q @ Wq^T + bias (split-bf16, ldmatrix) ----------------
#define TROW1 144   /* 72 bf16 per row; stride 36 words -> conflict-free ldsm */
#define K1A_SMEM (4 * 128 * TROW1)
__global__ __launch_bounds__(256, 2) void k1_ctx(const float* __restrict__ q,
                                                 const float* __restrict__ wq,
                                                 const float* __restrict__ bias)
{
    extern __shared__ char sm1[];
    char* sQh = sm1;
    char* sQl = sm1 + 128 * TROW1;
    char* sWh = sm1 + 2 * 128 * TROW1;
    char* sWl = sm1 + 3 * 128 * TROW1;
    const uint32_t uQh = smem_to_u32(sQh);
    const uint32_t uQl = smem_to_u32(sQl);
    const uint32_t uWh = smem_to_u32(sWh);
    const uint32_t uWl = smem_to_u32(sWl);

    const int tid  = threadIdx.x;
    const int w    = tid >> 5;
    const int lane = tid & 31;
    const int grp  = lane >> 2;
    const int qd   = lane & 3;
    const int rb   = blockIdx.x * 128;

    const int sel = lane >> 3, r8 = lane & 7;
    const uint32_t aOff = (uint32_t)(w * 16 + ((sel & 1) << 3) + r8) * TROW1 + ((sel >> 1) << 4);
    const uint32_t bOff = (uint32_t)(((sel >> 1) << 3) + r8) * TROW1 + ((sel & 1) << 4);

    float acc[16][4];
    #pragma unroll
    for (int i = 0; i < 16; i++) { acc[i][0] = acc[i][1] = acc[i][2] = acc[i][3] = 0.f; }

    for (int kt = 0; kt < 16; kt++) {
        const int kb = kt * 64;
        __syncthreads();
        #pragma unroll
        for (int u = 0; u < 8; u++) {
            int idx = tid + u * 256;
            int row = idx >> 4, c4 = (idx & 15) * 4;
            float4 v = *reinterpret_cast<const float4*>(q + (size_t)(rb + row) * DM + kb + c4);
            uint32_t h01, l01, h23, l23;
            split_pair(v.x, v.y, h01, l01);
            split_pair(v.z, v.w, h23, l23);
            *reinterpret_cast<uint32_t*>(sQh + row * TROW1 + c4 * 2)     = h01;
            *reinterpret_cast<uint32_t*>(sQh + row * TROW1 + c4 * 2 + 4) = h23;
            *reinterpret_cast<uint32_t*>(sQl + row * TROW1 + c4 * 2)     = l01;
            *reinterpret_cast<uint32_t*>(sQl + row * TROW1 + c4 * 2 + 4) = l23;

            float4 wv = make_float4(0.f, 0.f, 0.f, 0.f);
            if (row < HD)
                wv = *reinterpret_cast<const float4*>(wq + (size_t)row * DM + kb + c4);
            split_pair(wv.x, wv.y, h01, l01);
            split_pair(wv.z, wv.w, h23, l23);
            *reinterpret_cast<uint32_t*>(sWh + row * TROW1 + c4 * 2)     = h01;
            *reinterpret_cast<uint32_t*>(sWh + row * TROW1 + c4 * 2 + 4) = h23;
            *reinterpret_cast<uint32_t*>(sWl + row * TROW1 + c4 * 2)     = l01;
            *reinterpret_cast<uint32_t*>(sWl + row * TROW1 + c4 * 2 + 4) = l23;
        }
        __syncthreads();

        #pragma unroll
        for (int ks = 0; ks < 4; ks++) {
            uint32_t ah0, ah1, ah2, ah3, al0, al1, al2, al3;
            ldsm_x4(ah0, ah1, ah2, ah3, uQh + aOff + ks * 32);
            ldsm_x4(al0, al1, al2, al3, uQl + aOff + ks * 32);
            #pragma unroll
            for (int ntp = 0; ntp < 8; ntp++) {
                uint32_t bh0, bh1, bh2, bh3, bl0, bl1, bl2, bl3;
                const uint32_t bb = (uint32_t)(ntp * 16) * TROW1 + bOff + ks * 32;
                ldsm_x4(bh0, bh1, bh2, bh3, uWh + bb);
                ldsm_x4(bl0, bl1, bl2, bl3, uWl + bb);
                mma16816(acc[2 * ntp],     ah0, ah1, ah2, ah3, bh0, bh1);
                mma16816(acc[2 * ntp],     ah0, ah1, ah2, ah3, bl0, bl1);
                mma16816(acc[2 * ntp],     al0, al1, al2, al3, bh0, bh1);
                mma16816(acc[2 * ntp + 1], ah0, ah1, ah2, ah3, bh2, bh3);
                mma16816(acc[2 * ntp + 1], ah0, ah1, ah2, ah3, bl2, bl3);
                mma16816(acc[2 * ntp + 1], al0, al1, al2, al3, bh2, bh3);
            }
        }
    }

    const int R0 = rb + w * 16 + grp, R1 = R0 + 8;
    #pragma unroll
    for (int nt = 0; nt < 16; nt++) {
        int c = nt * 8 + 2 * qd;
        float b0 = (c     < HD) ? __ldg(bias + c)     : 0.f;
        float b1 = (c + 1 < HD) ? __ldg(bias + c + 1) : 0.f;
        float v00 = acc[nt][0] + b0, v01 = acc[nt][1] + b1;
        float v10 = acc[nt][2] + b0, v11 = acc[nt][3] + b1;
        *reinterpret_cast<float2*>(g_CTX + (size_t)R0 * HDP + c) = make_float2(v00, v01);
        *reinterpret_cast<float2*>(g_CTX + (size_t)R1 * HDP + c) = make_float2(v10, v11);
        uint32_t h, l;
        split_pair(v00, v01, h, l);
        *reinterpret_cast<uint32_t*>(g_CH + (size_t)R0 * HDP + c) = h;
        *reinterpret_cast<uint32_t*>(g_CL + (size_t)R0 * HDP + c) = l;
        split_pair(v10, v11, h, l);
        *reinterpret_cast<uint32_t*>(g_CH + (size_t)R1 * HDP + c) = h;
        *reinterpret_cast<uint32_t*>(g_CL + (size_t)R1 * HDP + c) = l;
    }
}

// ---------------- kernel 1b: trans = ctx @ DW, norms, kn, trans splits ----------------
__global__ __launch_bounds__(128) void k1_trans(const float* __restrict__ prec)
{
    __shared__ float cs[128 * 16];
    __shared__ float red[64];
    const int n  = threadIdx.x;
    const int rb = blockIdx.x * 16;

    #pragma unroll
    for (int u = 0; u < 16; u++) {
        int idx = n + u * 128;
        int r = idx >> 7, k = idx & 127;
        cs[k * 16 + r] = g_CTX[(size_t)(rb + r) * HDP + k];
    }
    __syncthreads();

    float acc[16];
    #pragma unroll
    for (int r = 0; r < 16; r++) acc[r] = 0.f;

    for (int k = 0; k < HDP; k++) {
        float dw = g_DW[k * HDP + n];
        const float4* c4 = reinterpret_cast<const float4*>(cs + k * 16);
        float4 a = c4[0], b = c4[1], c = c4[2], d = c4[3];
        acc[0]  = fmaf(a.x, dw, acc[0]);  acc[1]  = fmaf(a.y, dw, acc[1]);
        acc[2]  = fmaf(a.z, dw, acc[2]);  acc[3]  = fmaf(a.w, dw, acc[3]);
        acc[4]  = fmaf(b.x, dw, acc[4]);  acc[5]  = fmaf(b.y, dw, acc[5]);
        acc[6]  = fmaf(b.z, dw, acc[6]);  acc[7]  = fmaf(b.w, dw, acc[7]);
        acc[8]  = fmaf(c.x, dw, acc[8]);  acc[9]  = fmaf(c.y, dw, acc[9]);
        acc[10] = fmaf(c.z, dw, acc[10]); acc[11] = fmaf(c.w, dw, acc[11]);
        acc[12] = fmaf(d.x, dw, acc[12]); acc[13] = fmaf(d.y, dw, acc[13]);
        acc[14] = fmaf(d.z, dw, acc[14]); acc[15] = fmaf(d.w, dw, acc[15]);
    }

    const int lane = n & 31, wrp = n >> 5;
    #pragma unroll
    for (int r = 0; r < 16; r++) {
        float pr = acc[r] * cs[n * 16 + r];
        #pragma unroll
        for (int o = 16; o > 0; o >>= 1) pr += __shfl_xor_sync(0xffffffffu, pr, o);
        if (lane == 0) red[r * 4 + wrp] = pr;
    }
    __syncthreads();
    if (n < 16) {
        float p  = __ldg(prec);
        float nm = red[n * 4] + red[n * 4 + 1] + red[n * 4 + 2] + red[n * 4 + 3];
        g_KN[rb + n] = -0.5f * p * p * nm;
    }

    #pragma unroll
    for (int r = 0; r < 16; r++) {
        float v = acc[r];
        __nv_bfloat16 h = __float2bfloat16(v);
        __nv_bfloat16 l = __float2bfloat16(v - __bfloat162float(h));
        g_TH[(size_t)(rb + r) * HDP + n] = h;
        g_TL[(size_t)(rb + r) * HDP + n] = l;
    }
}

// ---------------- kernel 2: single-pass Gram + RBF, cp.async-pipelined B ----------------
// 64 A-rows per CTA (grid 256), 64-row B j-tiles double-buffered via cp.async.
// SMEM: A hi/lo (2x17408) + B 2 bufs x (hi+lo 2x17408) + kn 2x256 + sums = ~105 KB.
#define TROW 272
#define T64_B (64 * TROW)        /* 17408 */
#define NJT 32                   /* 2048 / 64 */
#define K2_SMEM_BYTES (2 * T64_B + 4 * T64_B + 1024 + 512)

__global__ __launch_bounds__(256, 2) void k2_attn(const float* __restrict__ prec,
                                                  float* __restrict__ out)
{
    extern __shared__ char sm2[];
    char* sAh = sm2;
    char* sAl = sm2 + T64_B;
    char* sB  = sm2 + 2 * T64_B;                 // [buf][hi|lo] each T64_B
    float* sKnj0 = reinterpret_cast<float*>(sm2 + 6 * T64_B);        // [64]
    float* sKnj1 = reinterpret_cast<float*>(sm2 + 6 * T64_B + 256);  // [64]
    float* sSum  = reinterpret_cast<float*>(sm2 + 6 * T64_B + 1024); // [128]

    const uint32_t uAh = smem_to_u32(sAh);
    const uint32_t uAl = smem_to_u32(sAl);
    const uint32_t uB  = smem_to_u32(sB);
    const uint32_t uKn0 = smem_to_u32(sKnj0);
    const uint32_t uKn1 = smem_to_u32(sKnj1);

    const int tid  = threadIdx.x;
    const int wid  = tid >> 5;
    const int lane = tid & 31;
    const int grp  = lane >> 2;
    const int qd   = lane & 3;
    const int wr   = wid & 3;        // row group: rows wr*16 .. wr*16+15
    const int wc   = wid >> 2;       // col half of 64: cols wc*32 .. wc*32+31
    const int bt   = blockIdx.x;
    const int b    = bt >> 5;
    const int rt   = bt & 31;
    const int rowg = b * L_SEQ + rt * 64;

    const int sel = lane >> 3, r8 = lane & 7;
    const uint32_t aOff = (uint32_t)(wr * 16 + ((sel & 1) << 3) + r8) * TROW + ((sel >> 1) << 4);
    const uint32_t bOff = (uint32_t)(((sel >> 1) << 3) + r8) * TROW + ((sel & 1) << 4);

    // ---- prefetch B tile 0 (buf 0) + kn(0) via cp.async ----
    {
        const int jb = b * L_SEQ;
        for (int idx = tid; idx < 64 * 16; idx += 256) {
            int row = idx >> 4, c8 = idx & 15;
            cp_async16(uB + row * TROW + c8 * 16,
                       g_CH + (size_t)(jb + row) * HDP + c8 * 8);
            cp_async16(uB + T64_B + row * TROW + c8 * 16,
                       g_CL + (size_t)(jb + row) * HDP + c8 * 8);
        }
        if (tid < 16) cp_async16(uKn0 + tid * 16, g_KN + jb + tid * 4);
        CP_COMMIT();
    }

    // ---- A tiles (resident, 64 rows) ----
    for (int idx = tid; idx < 64 * 16; idx += 256) {
        int row = idx >> 4, c8 = idx & 15;
        *reinterpret_cast<uint4*>(sAh + row * TROW + c8 * 16) =
            *reinterpret_cast<const uint4*>(g_TH + (size_t)(rowg + row) * HDP + c8 * 8);
        *reinterpret_cast<uint4*>(sAl + row * TROW + c8 * 16) =
            *reinterpret_cast<const uint4*>(g_TL + (size_t)(rowg + row) * HDP + c8 * 8);
    }

    const float p     = __ldg(prec);
    const float scale = p * p;
    const int   ra    = wr * 16 + grp;          // local row 0..63
    const int   iloc0 = rt * 64 + ra;
    const int   iloc1 = iloc0 + 8;
    const float kni0  = g_KN[rowg + ra];
    const float kni1  = g_KN[rowg + ra + 8];
    const size_t outbase = (size_t)b * L_SEQ * L_SEQ;
    const float E = 2.718281828459045f;

    float sum0 = 0.f, sum1 = 0.f;

    for (int jt = 0; jt < NJT; jt++) {
        const int cur = jt & 1;
        const int nxt = cur ^ 1;
        __syncthreads();   // all threads done reading buf[nxt] (iter jt-1) and A stores visible

        if (jt + 1 < NJT) {
            const int jb = b * L_SEQ + (jt + 1) * 64;
            const uint32_t dB = uB + (uint32_t)nxt * (2 * T64_B);
            for (int idx = tid; idx < 64 * 16; idx += 256) {
                int row = idx >> 4, c8 = idx & 15;
                cp_async16(dB + row * TROW + c8 * 16,
                           g_CH + (size_t)(jb + row) * HDP + c8 * 8);
                cp_async16(dB + T64_B + row * TROW + c8 * 16,
                           g_CL + (size_t)(jb + row) * HDP + c8 * 8);
            }
            if (tid < 16) cp_async16((nxt ? uKn1 : uKn0) + tid * 16, g_KN + jb + tid * 4);
            CP_COMMIT();
            CP_WAIT(1);    // current tile's group complete; next stays in flight
        } else {
            CP_WAIT(0);
        }
        __syncthreads();   // current buffer visible to all threads

        const uint32_t uBh = uB + (uint32_t)cur * (2 * T64_B);
        const uint32_t uBl = uBh + T64_B;
        const float* knj = cur ? sKnj1 : sKnj0;

        float acc[4][4];
        #pragma unroll
        for (int i = 0; i < 4; i++) { acc[i][0] = acc[i][1] = acc[i][2] = acc[i][3] = 0.f; }

        #pragma unroll
        for (int ks = 0; ks < 8; ks++) {
            uint32_t ah0, ah1, ah2, ah3, al0, al1, al2, al3;
            ldsm_x4(ah0, ah1, ah2, ah3, uAh + aOff + ks * 32);
            ldsm_x4(al0, al1, al2, al3, uAl + aOff + ks * 32);
            #pragma unroll
            for (int ntp = 0; ntp < 2; ntp++) {
                uint32_t bh0, bh1, bh2, bh3, bl0, bl1, bl2, bl3;
                const uint32_t bb = (uint32_t)(wc * 32 + ntp * 16) * TROW + bOff + ks * 32;
                ldsm_x4(bh0, bh1, bh2, bh3, uBh + bb);
                ldsm_x4(bl0, bl1, bl2, bl3, uBl + bb);
                mma16816(acc[2 * ntp],     ah0, ah1, ah2, ah3, bh0, bh1);
                mma16816(acc[2 * ntp],     ah0, ah1, ah2, ah3, bl0, bl1);
                mma16816(acc[2 * ntp],     al0, al1, al2, al3, bh0, bh1);
                mma16816(acc[2 * ntp + 1], ah0, ah1, ah2, ah3, bh2, bh3);
                mma16816(acc[2 * ntp + 1], ah0, ah1, ah2, ah3, bl2, bl3);
                mma16816(acc[2 * ntp + 1], al0, al1, al2, al3, bh2, bh3);
            }
        }

        // epilogue: y = exp(exp(kn_i + kn_j + scale*g)); store unnormalized; accumulate sums
        #pragma unroll
        for (int nt = 0; nt < 4; nt++) {
            const int c    = wc * 32 + nt * 8 + 2 * qd;
            const int jloc = jt * 64 + c;
            const float knj0 = knj[c], knj1 = knj[c + 1];
            float t00 = fmaf(scale, acc[nt][0], kni0 + knj0);
            float t01 = fmaf(scale, acc[nt][1], kni0 + knj1);
            float t10 = fmaf(scale, acc[nt][2], kni1 + knj0);
            float t11 = fmaf(scale, acc[nt][3], kni1 + knj1);
            float y00 = __expf(__expf(t00));
            float y01 = __expf(__expf(t01));
            float y10 = __expf(__expf(t10));
            float y11 = __expf(__expf(t11));
            if (iloc0 == jloc)     y00 = E;
            if (iloc0 == jloc + 1) y01 = E;
            if (iloc1 == jloc)     y10 = E;
            if (iloc1 == jloc + 1) y11 = E;
            sum0 += y00 + y01;
            sum1 += y10 + y11;
            *reinterpret_cast<float2*>(out + outbase + (size_t)iloc0 * L_SEQ + jloc) =
                make_float2(y00, y01);
            *reinterpret_cast<float2*>(out + outbase + (size_t)iloc1 * L_SEQ + jloc) =
                make_float2(y10, y11);
        }
    }

    // ---- row sums: quad-reduce, combine col halves via smem ----
    sum0 += __shfl_xor_sync(0xffffffffu, sum0, 1);
    sum0 += __shfl_xor_sync(0xffffffffu, sum0, 2);
    sum1 += __shfl_xor_sync(0xffffffffu, sum1, 1);
    sum1 += __shfl_xor_sync(0xffffffffu, sum1, 2);
    __syncthreads();
    if (qd == 0) {
        sSum[wc * 64 + ra]     = sum0;
        sSum[wc * 64 + ra + 8] = sum1;
    }
    __syncthreads();
    if (tid < 64) sSum[tid] = 1.0f / (sSum[tid] + sSum[64 + tid]);
    __syncthreads();

    // ---- normalize readback: this CTA's 64x2048 strip (L2-hot) ----
    float4* strip = reinterpret_cast<float4*>(out + outbase + (size_t)(rt * 64) * L_SEQ);
    #pragma unroll 4
    for (int it = tid; it < 64 * 512; it += 256) {
        const int row = it >> 9;
        const float s = sSum[row];
        float4 v = strip[it];
        v.x *= s; v.y *= s; v.z *= s; v.w *= s;
        strip[it] = v;
    }
}

// ---------------- launch ----------------
extern "C" void kernel_launch(void* const* d_in, const int* in_sizes, int n_in,
                              void* d_out, int out_size)
{
    (void)in_sizes; (void)n_in; (void)out_size;
    const float* q    = (const float*)d_in[0];
    // d_in[1] = key (unused by the reference computation)
    const float* wq   = (const float*)d_in[2];
    const float* bias = (const float*)d_in[3];
    const float* W    = (const float*)d_in[4];
    const float* prec = (const float*)d_in[5];
    float* out = (float*)d_out;

    cudaFuncSetAttribute(k1_ctx,  cudaFuncAttributeMaxDynamicSharedMemorySize, K1A_SMEM);
    cudaFuncSetAttribute(k2_attn, cudaFuncAttributeMaxDynamicSharedMemorySize, K2_SMEM_BYTES);

    k0_dw<<<HDP, HDP>>>(W);
    k1_ctx<<<NROWS / 128, 256, K1A_SMEM>>>(q, wq, bias);
    k1_trans<<<NROWS / 16, 128>>>(prec);
    k2_attn<<<NROWS / 64, 256, K2_SMEM_BYTES>>>(prec, out);
}